// round 1
// baseline (speedup 1.0000x reference)
#include <cuda_runtime.h>
#include <cstdint>

#define NB   8192
#define NS   100
#define NE   64
#define NH1  128
#define NH2  64
#define NF   128   // k' = [k, k*q] dimension

// -------- device scratch (alloc-free) --------
__device__ float g_Wcat[NF * NH1];   // [f][h]: rows 0..63 = W0b - W0d, rows 64..127 = W0c
__device__ float g_Wq[NE * NH1];     // [e][h]: W0a + W0d

// -------- f32x2 packed-FMA helpers (FFMA2; PTX-only on sm_103a) --------
__device__ __forceinline__ unsigned long long pack2(float lo, float hi) {
    unsigned long long r;
    asm("mov.b64 %0, {%1, %2};" : "=l"(r) : "f"(lo), "f"(hi));
    return r;
}
__device__ __forceinline__ void fma2(unsigned long long& d, unsigned long long a,
                                     unsigned long long b) {
    asm("fma.rn.f32x2 %0, %1, %2, %0;" : "+l"(d) : "l"(a), "l"(b));
}
__device__ __forceinline__ float2 unpack2(unsigned long long v) {
    float lo, hi;
    asm("mov.b64 {%0, %1}, %2;" : "=f"(lo), "=f"(hi) : "l"(v));
    return make_float2(lo, hi);
}

// -------- prelude: fold W0 into Wcat / Wq --------
__global__ void prep_kernel(const float* __restrict__ W0) {
    int idx = blockIdx.x * blockDim.x + threadIdx.x;
    if (idx >= NF * NH1) return;
    int e = idx >> 7, h = idx & 127;
    float v;
    if (e < 64) v = W0[(64 + e) * NH1 + h] - W0[(192 + e) * NH1 + h];
    else        v = W0[(128 + (e - 64)) * NH1 + h];
    g_Wcat[idx] = v;
    if (e < 64) g_Wq[idx] = W0[e * NH1 + h] + W0[(192 + e) * NH1 + h];
}

// -------- fused per-batch kernel: 1 CTA = 1 batch, 512 threads --------
// smem layout (floats):
//  sWcat 16384 | sW1 8192 | sKp 12800 | sH0 12800 | sH1 6400 |
//  sC 128 | sQ 64 | sW2 64 | sB1 64 | sScore 104        = 57000 floats = 228000 B
__global__ __launch_bounds__(512, 1)
void din_kernel(const float* __restrict__ q_g,
                const float* __restrict__ keys_g,
                const int*   __restrict__ klen_g,
                const float* __restrict__ b0_g,
                const float* __restrict__ W1_g,
                const float* __restrict__ b1_g,
                const float* __restrict__ W2_g,
                const float* __restrict__ b2_g,
                float* __restrict__ out_g,
                float* __restrict__ attn_g) {
    extern __shared__ float sm[];
    float* sWcat  = sm;                 // 16384
    float* sW1    = sWcat + 16384;      // 8192
    float* sKp    = sW1 + 8192;         // 12800  [s][f]  (f<64 = keys row)
    float* sH0    = sKp + 12800;        // 12800  [s][h]
    float* sH1    = sH0 + 12800;        // 6400   [s][j]
    float* sC     = sH1 + 6400;         // 128
    float* sQ     = sC + 128;           // 64
    float* sW2    = sQ + 64;            // 64
    float* sB1    = sW2 + 64;           // 64
    float* sScore = sB1 + 64;           // 104

    const int b = blockIdx.x;
    const int t = threadIdx.x;
    const int len = klen_g[b];
    const float b2v = b2_g[0];

    // ---- load shared weights + q ----
    for (int i = t; i < NF * NH1; i += 512) sWcat[i] = g_Wcat[i];
    for (int i = t; i < NH1 * NH2; i += 512) sW1[i] = W1_g[i];
    if (t < 64) { sQ[t] = q_g[b * NE + t]; sW2[t] = W2_g[t]; sB1[t] = b1_g[t]; }
    __syncthreads();

    // ---- c[h] = b0[h] + sum_e q[e] * Wq[e][h]  (Wq streamed from L2) ----
    if (t < NH1) {
        float acc = b0_g[t];
        #pragma unroll 8
        for (int e = 0; e < NE; e++) acc = fmaf(sQ[e], g_Wq[e * NH1 + t], acc);
        sC[t] = acc;
    }
    // ---- build K' tile: [k, k*q] ----
    for (int i = t; i < NS * NE; i += 512) {
        int s = i >> 6, e = i & 63;
        float k = keys_g[((size_t)b * NS + s) * NE + e];
        sKp[s * NF + e]      = k;
        sKp[s * NF + 64 + e] = k * sQ[e];
    }
    __syncthreads();

    // ---- GEMM1: H0[s][h] = relu(c[h] + sum_f Kp[s][f] * Wcat[f][h]) ----
    {
        const int tx = t & 31, ty = t >> 5;   // TN=4 (h), 16 row-groups
        const int h = tx * 4;
        unsigned long long a0[7], a1[7];
        int aoff[7];
        #pragma unroll
        for (int i = 0; i < 7; i++) {
            a0[i] = 0ULL; a1[i] = 0ULL;
            int s = ty + i * 16; if (s > NS - 1) s = NS - 1;
            aoff[i] = s * NF;
        }
        #pragma unroll 2
        for (int f = 0; f < NF; f++) {
            float4 w = *(const float4*)&sWcat[f * NH1 + h];
            unsigned long long w01 = pack2(w.x, w.y);
            unsigned long long w23 = pack2(w.z, w.w);
            #pragma unroll
            for (int i = 0; i < 7; i++) {
                float a = sKp[aoff[i] + f];
                unsigned long long aa = pack2(a, a);
                fma2(a0[i], aa, w01);
                fma2(a1[i], aa, w23);
            }
        }
        float c0 = sC[h], c1 = sC[h + 1], c2 = sC[h + 2], c3 = sC[h + 3];
        #pragma unroll
        for (int i = 0; i < 7; i++) {
            int s = ty + i * 16;
            if (s < NS) {
                float2 v0 = unpack2(a0[i]), v1 = unpack2(a1[i]);
                sH0[s * NH1 + h]     = fmaxf(v0.x + c0, 0.f);
                sH0[s * NH1 + h + 1] = fmaxf(v0.y + c1, 0.f);
                sH0[s * NH1 + h + 2] = fmaxf(v1.x + c2, 0.f);
                sH0[s * NH1 + h + 3] = fmaxf(v1.y + c3, 0.f);
            }
        }
    }
    __syncthreads();

    // ---- GEMM2: H1[s][j] = relu(b1[j] + sum_h H0[s][h] * W1[h][j]) ----
    {
        const int tx = t & 15, ty = t >> 4;   // TN=4 (j), 32 row-groups
        const int j = tx * 4;
        unsigned long long a0[4], a1[4];
        int aoff[4];
        #pragma unroll
        for (int i = 0; i < 4; i++) {
            a0[i] = 0ULL; a1[i] = 0ULL;
            int s = ty + i * 32; if (s > NS - 1) s = NS - 1;
            aoff[i] = s * NH1;
        }
        #pragma unroll 2
        for (int hh = 0; hh < NH1; hh++) {
            float4 w = *(const float4*)&sW1[hh * NH2 + j];
            unsigned long long w01 = pack2(w.x, w.y);
            unsigned long long w23 = pack2(w.z, w.w);
            #pragma unroll
            for (int i = 0; i < 4; i++) {
                float a = sH0[aoff[i] + hh];
                unsigned long long aa = pack2(a, a);
                fma2(a0[i], aa, w01);
                fma2(a1[i], aa, w23);
            }
        }
        float bb0 = sB1[j], bb1 = sB1[j + 1], bb2 = sB1[j + 2], bb3 = sB1[j + 3];
        #pragma unroll
        for (int i = 0; i < 4; i++) {
            int s = ty + i * 32;
            if (s < NS) {
                float2 v0 = unpack2(a0[i]), v1 = unpack2(a1[i]);
                sH1[s * NH2 + j]     = fmaxf(v0.x + bb0, 0.f);
                sH1[s * NH2 + j + 1] = fmaxf(v0.y + bb1, 0.f);
                sH1[s * NH2 + j + 2] = fmaxf(v1.x + bb2, 0.f);
                sH1[s * NH2 + j + 3] = fmaxf(v1.y + bb3, 0.f);
            }
        }
    }
    __syncthreads();

    // ---- scores[s] = H1[s] . W2 + b2 (deterministic warp reduction) ----
    {
        const int w = t >> 5, lane = t & 31;
        const float w2a = sW2[lane], w2b = sW2[32 + lane];
        for (int s = w; s < NS; s += 16) {
            float v = sH1[s * NH2 + lane] * w2a + sH1[s * NH2 + 32 + lane] * w2b;
            #pragma unroll
            for (int off = 16; off; off >>= 1) v += __shfl_xor_sync(0xffffffffu, v, off);
            if (lane == 0) sScore[s] = v + b2v;
        }
    }
    __syncthreads();

    // ---- masked softmax over sScore[0..NS) by warp 0 ----
    if (t < 32) {
        float m = -1e30f;
        for (int s = t; s < NS; s += 32) {
            float v = (s < len) ? sScore[s] : -1e30f;
            m = fmaxf(m, v);
        }
        #pragma unroll
        for (int off = 16; off; off >>= 1) m = fmaxf(m, __shfl_xor_sync(0xffffffffu, m, off));
        float sum = 0.f;
        for (int s = t; s < NS; s += 32) {
            float v = (s < len) ? expf(sScore[s] - m) : 0.f;
            sScore[s] = v;
            sum += v;
        }
        #pragma unroll
        for (int off = 16; off; off >>= 1) sum += __shfl_xor_sync(0xffffffffu, sum, off);
        float inv = 1.f / sum;
        for (int s = t; s < NS; s += 32) sScore[s] *= inv;
    }
    __syncthreads();

    // ---- out[e] = sum_s attn[s] * keys[s][e]  (keys = first 64 cols of Kp) ----
    {
        const int e = t & 63, g = t >> 6;   // 8 groups of s
        float acc = 0.f;
        for (int s = g; s < NS; s += 8) acc = fmaf(sScore[s], sKp[s * NF + e], acc);
        sH0[g * 64 + e] = acc;              // H0 reused as scratch
    }
    __syncthreads();
    if (t < 64) {
        float o = 0.f;
        #pragma unroll
        for (int g = 0; g < 8; g++) o += sH0[g * 64 + t];
        out_g[(size_t)b * NE + t] = o;
    }
    if (attn_g && t < NS) attn_g[(size_t)b * NS + t] = sScore[t];
}

extern "C" void kernel_launch(void* const* d_in, const int* in_sizes, int n_in,
                              void* d_out, int out_size) {
    const float* query = (const float*)d_in[0];
    const float* keys  = (const float*)d_in[1];
    const int*   klen  = (const int*)  d_in[2];
    const float* W0    = (const float*)d_in[3];
    const float* b0    = (const float*)d_in[4];
    const float* W1    = (const float*)d_in[5];
    const float* b1    = (const float*)d_in[6];
    const float* W2    = (const float*)d_in[7];
    const float* b2    = (const float*)d_in[8];

    float* outp  = (float*)d_out;
    float* attnp = (out_size >= NB * NE + NB * NS) ? outp + (size_t)NB * NE : nullptr;

    const int smem_bytes = 57000 * (int)sizeof(float);  // 228000 B
    cudaFuncSetAttribute(din_kernel, cudaFuncAttributeMaxDynamicSharedMemorySize,
                         smem_bytes);

    prep_kernel<<<(NF * NH1 + 511) / 512, 512>>>(W0);
    din_kernel<<<NB, 512, smem_bytes>>>(query, keys, klen, b0, W1, b1, W2, b2,
                                        outp, attnp);
}

// round 2
// speedup vs baseline: 1.0064x; 1.0064x over previous
#include <cuda_runtime.h>
#include <cstdint>

#define NB   8192
#define NS   100
#define NE   64
#define NH1  128
#define NH2  64
#define NF   128   // k' = [k, k*q] dimension

// -------- device scratch (alloc-free) --------
__device__ float g_Wcat[NF * NH1];   // [f][h]: rows 0..63 = W0b - W0d, rows 64..127 = W0c
__device__ float g_Wq[NE * NH1];     // [e][h]: W0a + W0d

// -------- f32x2 packed-FMA helpers (FFMA2; PTX-only on sm_103a) --------
__device__ __forceinline__ unsigned long long pack2(float lo, float hi) {
    unsigned long long r;
    asm("mov.b64 %0, {%1, %2};" : "=l"(r) : "f"(lo), "f"(hi));
    return r;
}
__device__ __forceinline__ void fma2(unsigned long long& d, unsigned long long a,
                                     unsigned long long b) {
    asm("fma.rn.f32x2 %0, %1, %2, %0;" : "+l"(d) : "l"(a), "l"(b));
}
__device__ __forceinline__ float2 unpack2(unsigned long long v) {
    float lo, hi;
    asm("mov.b64 {%0, %1}, %2;" : "=f"(lo), "=f"(hi) : "l"(v));
    return make_float2(lo, hi);
}

// -------- prelude: fold W0 into Wcat / Wq --------
__global__ void prep_kernel(const float* __restrict__ W0) {
    int idx = blockIdx.x * blockDim.x + threadIdx.x;
    if (idx >= NF * NH1) return;
    int e = idx >> 7, h = idx & 127;
    float v;
    if (e < 64) v = W0[(64 + e) * NH1 + h] - W0[(192 + e) * NH1 + h];
    else        v = W0[(128 + (e - 64)) * NH1 + h];
    g_Wcat[idx] = v;
    if (e < 64) g_Wq[idx] = W0[e * NH1 + h] + W0[(192 + e) * NH1 + h];
}

// -------- fused per-batch kernel: 1 CTA = 1 batch, 512 threads --------
// smem layout (floats):
//  sWcat 16384 | sW1 8192 | sKp 12800 | sH0 12800 | sH1 6400 |
//  sC 128 | sQ 64 | sW2 64 | sB1 64 | sScore 104        = 57000 floats = 228000 B
__global__ __launch_bounds__(512, 1)
void din_kernel(const float* __restrict__ q_g,
                const float* __restrict__ keys_g,
                const int*   __restrict__ klen_g,
                const float* __restrict__ b0_g,
                const float* __restrict__ W1_g,
                const float* __restrict__ b1_g,
                const float* __restrict__ W2_g,
                const float* __restrict__ b2_g,
                float* __restrict__ out_g,
                float* __restrict__ attn_g) {
    extern __shared__ float sm[];
    float* sWcat  = sm;                 // 16384
    float* sW1    = sWcat + 16384;      // 8192
    float* sKp    = sW1 + 8192;         // 12800  [s][f]  (f<64 = keys row)
    float* sH0    = sKp + 12800;        // 12800  [s][h]
    float* sH1    = sH0 + 12800;        // 6400   [s][j]
    float* sC     = sH1 + 6400;         // 128
    float* sQ     = sC + 128;           // 64
    float* sW2    = sQ + 64;            // 64
    float* sB1    = sW2 + 64;           // 64
    float* sScore = sB1 + 64;           // 104

    const int b = blockIdx.x;
    const int t = threadIdx.x;
    const int len = klen_g[b];
    const float b2v = b2_g[0];

    // ---- load shared weights + q ----
    for (int i = t; i < NF * NH1; i += 512) sWcat[i] = g_Wcat[i];
    for (int i = t; i < NH1 * NH2; i += 512) sW1[i] = W1_g[i];
    if (t < 64) { sQ[t] = q_g[b * NE + t]; sW2[t] = W2_g[t]; sB1[t] = b1_g[t]; }
    __syncthreads();

    // ---- c[h] = b0[h] + sum_e q[e] * Wq[e][h]  (Wq streamed from L2) ----
    if (t < NH1) {
        float acc = b0_g[t];
        #pragma unroll 8
        for (int e = 0; e < NE; e++) acc = fmaf(sQ[e], g_Wq[e * NH1 + t], acc);
        sC[t] = acc;
    }
    // ---- build K' tile: [k, k*q] ----
    for (int i = t; i < NS * NE; i += 512) {
        int s = i >> 6, e = i & 63;
        float k = keys_g[((size_t)b * NS + s) * NE + e];
        sKp[s * NF + e]      = k;
        sKp[s * NF + 64 + e] = k * sQ[e];
    }
    __syncthreads();

    // ---- GEMM1: H0[s][h] = relu(c[h] + sum_f Kp[s][f] * Wcat[f][h]) ----
    {
        const int tx = t & 31, ty = t >> 5;   // TN=4 (h), 16 row-groups
        const int h = tx * 4;
        unsigned long long a0[7], a1[7];
        int aoff[7];
        #pragma unroll
        for (int i = 0; i < 7; i++) {
            a0[i] = 0ULL; a1[i] = 0ULL;
            int s = ty + i * 16; if (s > NS - 1) s = NS - 1;
            aoff[i] = s * NF;
        }
        #pragma unroll 2
        for (int f = 0; f < NF; f++) {
            float4 w = *(const float4*)&sWcat[f * NH1 + h];
            unsigned long long w01 = pack2(w.x, w.y);
            unsigned long long w23 = pack2(w.z, w.w);
            #pragma unroll
            for (int i = 0; i < 7; i++) {
                float a = sKp[aoff[i] + f];
                unsigned long long aa = pack2(a, a);
                fma2(a0[i], aa, w01);
                fma2(a1[i], aa, w23);
            }
        }
        float c0 = sC[h], c1 = sC[h + 1], c2 = sC[h + 2], c3 = sC[h + 3];
        #pragma unroll
        for (int i = 0; i < 7; i++) {
            int s = ty + i * 16;
            if (s < NS) {
                float2 v0 = unpack2(a0[i]), v1 = unpack2(a1[i]);
                sH0[s * NH1 + h]     = fmaxf(v0.x + c0, 0.f);
                sH0[s * NH1 + h + 1] = fmaxf(v0.y + c1, 0.f);
                sH0[s * NH1 + h + 2] = fmaxf(v1.x + c2, 0.f);
                sH0[s * NH1 + h + 3] = fmaxf(v1.y + c3, 0.f);
            }
        }
    }
    __syncthreads();

    // ---- GEMM2: H1[s][j] = relu(b1[j] + sum_h H0[s][h] * W1[h][j]) ----
    {
        const int tx = t & 15, ty = t >> 4;   // TN=4 (j), 32 row-groups
        const int j = tx * 4;
        unsigned long long a0[4], a1[4];
        int aoff[4];
        #pragma unroll
        for (int i = 0; i < 4; i++) {
            a0[i] = 0ULL; a1[i] = 0ULL;
            int s = ty + i * 32; if (s > NS - 1) s = NS - 1;
            aoff[i] = s * NH1;
        }
        #pragma unroll 2
        for (int hh = 0; hh < NH1; hh++) {
            float4 w = *(const float4*)&sW1[hh * NH2 + j];
            unsigned long long w01 = pack2(w.x, w.y);
            unsigned long long w23 = pack2(w.z, w.w);
            #pragma unroll
            for (int i = 0; i < 4; i++) {
                float a = sH0[aoff[i] + hh];
                unsigned long long aa = pack2(a, a);
                fma2(a0[i], aa, w01);
                fma2(a1[i], aa, w23);
            }
        }
        float bb0 = sB1[j], bb1 = sB1[j + 1], bb2 = sB1[j + 2], bb3 = sB1[j + 3];
        #pragma unroll
        for (int i = 0; i < 4; i++) {
            int s = ty + i * 32;
            if (s < NS) {
                float2 v0 = unpack2(a0[i]), v1 = unpack2(a1[i]);
                sH1[s * NH2 + j]     = fmaxf(v0.x + bb0, 0.f);
                sH1[s * NH2 + j + 1] = fmaxf(v0.y + bb1, 0.f);
                sH1[s * NH2 + j + 2] = fmaxf(v1.x + bb2, 0.f);
                sH1[s * NH2 + j + 3] = fmaxf(v1.y + bb3, 0.f);
            }
        }
    }
    __syncthreads();

    // ---- scores[s] = H1[s] . W2 + b2 (deterministic warp reduction) ----
    {
        const int w = t >> 5, lane = t & 31;
        const float w2a = sW2[lane], w2b = sW2[32 + lane];
        for (int s = w; s < NS; s += 16) {
            float v = sH1[s * NH2 + lane] * w2a + sH1[s * NH2 + 32 + lane] * w2b;
            #pragma unroll
            for (int off = 16; off; off >>= 1) v += __shfl_xor_sync(0xffffffffu, v, off);
            if (lane == 0) sScore[s] = v + b2v;
        }
    }
    __syncthreads();

    // ---- masked softmax over sScore[0..NS) by warp 0 ----
    if (t < 32) {
        float m = -1e30f;
        for (int s = t; s < NS; s += 32) {
            float v = (s < len) ? sScore[s] : -1e30f;
            m = fmaxf(m, v);
        }
        #pragma unroll
        for (int off = 16; off; off >>= 1) m = fmaxf(m, __shfl_xor_sync(0xffffffffu, m, off));
        float sum = 0.f;
        for (int s = t; s < NS; s += 32) {
            float v = (s < len) ? expf(sScore[s] - m) : 0.f;
            sScore[s] = v;
            sum += v;
        }
        #pragma unroll
        for (int off = 16; off; off >>= 1) sum += __shfl_xor_sync(0xffffffffu, sum, off);
        float inv = 1.f / sum;
        for (int s = t; s < NS; s += 32) sScore[s] *= inv;
    }
    __syncthreads();

    // ---- out[e] = sum_s attn[s] * keys[s][e]  (keys = first 64 cols of Kp) ----
    {
        const int e = t & 63, g = t >> 6;   // 8 groups of s
        float acc = 0.f;
        for (int s = g; s < NS; s += 8) acc = fmaf(sScore[s], sKp[s * NF + e], acc);
        sH0[g * 64 + e] = acc;              // H0 reused as scratch
    }
    __syncthreads();
    if (t < 64) {
        float o = 0.f;
        #pragma unroll
        for (int g = 0; g < 8; g++) o += sH0[g * 64 + t];
        out_g[(size_t)b * NE + t] = o;
    }
    if (attn_g && t < NS) attn_g[(size_t)b * NS + t] = sScore[t];
}

extern "C" void kernel_launch(void* const* d_in, const int* in_sizes, int n_in,
                              void* d_out, int out_size) {
    const float* query = (const float*)d_in[0];
    const float* keys  = (const float*)d_in[1];
    const int*   klen  = (const int*)  d_in[2];
    const float* W0    = (const float*)d_in[3];
    const float* b0    = (const float*)d_in[4];
    const float* W1    = (const float*)d_in[5];
    const float* b1    = (const float*)d_in[6];
    const float* W2    = (const float*)d_in[7];
    const float* b2    = (const float*)d_in[8];

    float* outp  = (float*)d_out;
    float* attnp = (out_size >= NB * NE + NB * NS) ? outp + (size_t)NB * NE : nullptr;

    const int smem_bytes = 57000 * (int)sizeof(float);  // 228000 B
    cudaFuncSetAttribute(din_kernel, cudaFuncAttributeMaxDynamicSharedMemorySize,
                         smem_bytes);

    prep_kernel<<<(NF * NH1 + 511) / 512, 512>>>(W0);
    din_kernel<<<NB, 512, smem_bytes>>>(query, keys, klen, b0, W1, b1, W2, b2,
                                        outp, attnp);
}